// round 5
// baseline (speedup 1.0000x reference)
#include <cuda_runtime.h>
#include <cstdint>

#define NN 100000
#define EE 1600000
#define EQ 400000          // EE/4 (unroll-4 split)
#define DD 32
#define CUT_K 320000       // int(1600000 * 0.2)
#define EPS 1e-12f

// ---------------- scratch (static device globals; no allocation) ----------------
__device__ float     g_Y1[NN * DD];
__device__ float     g_Y2[NN * DD];
__device__ unsigned  g_key[EE];       // monotone uint key of cosine
__device__ float     g_rn[NN];        // 1 / max(||row||, eps)
__device__ float     g_norm[NN];      // clip(deg,1)^-0.5
__device__ int       g_deg[NN];
__device__ unsigned  g_h16[65536];    // 16-bit radix histogram (L2-resident)
__device__ unsigned  g_prefix;        // selected threshold key (built over 2 passes)
__device__ unsigned  g_kremain;       // final: #equal-to-threshold keys to drop
__device__ unsigned  g_ticket;        // tie-break ticket counter

// monotone float -> uint key (ascending float order == ascending unsigned order)
__device__ __forceinline__ unsigned fkey(float f) {
    unsigned u = __float_as_uint(f);
    return (u & 0x80000000u) ? ~u : (u | 0x80000000u);
}

// ---------------- kernels ----------------

// zero deg + h16 + Y1 + Y2 + selector scalars in one pass (grid 3125 x 256 = 800K thr)
__global__ void k_init() {
    int i = blockIdx.x * blockDim.x + threadIdx.x;
    ((float4*)g_Y1)[i] = make_float4(0.f, 0.f, 0.f, 0.f);
    ((float4*)g_Y2)[i] = make_float4(0.f, 0.f, 0.f, 0.f);
    if (i < NN) g_deg[i] = 0;
    if (i < 65536) g_h16[i] = 0;
    if (i == 0) { g_prefix = 0u; g_kremain = CUT_K; g_ticket = 0u; }
}

// int4-vectorized degree count
__global__ void k_deg(const int4* __restrict__ dst4) {
    int i = blockIdx.x * blockDim.x + threadIdx.x;
    if (i < EE / 4) {
        int4 d = dst4[i];
        atomicAdd(&g_deg[d.x], 1);
        atomicAdd(&g_deg[d.y], 1);
        atomicAdd(&g_deg[d.z], 1);
        atomicAdd(&g_deg[d.w], 1);
    }
}

// 8 lanes per node: inverse L2 row norm; optionally also deg-norm / selector re-arm
template <int DO_NORM, int RESET>
__global__ void k_rn(const float4* __restrict__ X4) {
    int gid  = blockIdx.x * blockDim.x + threadIdx.x;
    int node = gid >> 3;
    int sub  = gid & 7;
    float4 v = X4[node * 8 + sub];
    float s = v.x * v.x + v.y * v.y + v.z * v.z + v.w * v.w;
    s += __shfl_xor_sync(0xffffffffu, s, 1);
    s += __shfl_xor_sync(0xffffffffu, s, 2);
    s += __shfl_xor_sync(0xffffffffu, s, 4);
    if (sub == 0) {
        g_rn[node] = 1.0f / fmaxf(sqrtf(s), EPS);
        if (DO_NORM) {
            int d = g_deg[node];
            if (d < 1) d = 1;
            g_norm[node] = 1.0f / sqrtf((float)d);
        }
    }
    if (RESET && gid == 0) { g_prefix = 0u; g_kremain = CUT_K; g_ticket = 0u; }
}

// 8 lanes per edge, 4 edges per group; writes keys + fused radix pass-0 (top-16) hist
__global__ void k_cos(const float4* __restrict__ X4,
                      const int* __restrict__ src, const int* __restrict__ dst) {
    int gid = blockIdx.x * blockDim.x + threadIdx.x;
    int e0  = gid >> 3;
    int sub = gid & 7;

    int s0 = src[e0],          d0 = dst[e0];
    int s1 = src[e0 + EQ],     d1 = dst[e0 + EQ];
    int s2 = src[e0 + 2 * EQ], d2 = dst[e0 + 2 * EQ];
    int s3 = src[e0 + 3 * EQ], d3 = dst[e0 + 3 * EQ];

    float4 a0 = X4[s0 * 8 + sub], b0 = X4[d0 * 8 + sub];
    float4 a1 = X4[s1 * 8 + sub], b1 = X4[d1 * 8 + sub];
    float4 a2 = X4[s2 * 8 + sub], b2 = X4[d2 * 8 + sub];
    float4 a3 = X4[s3 * 8 + sub], b3 = X4[d3 * 8 + sub];

    float p0 = a0.x * b0.x + a0.y * b0.y + a0.z * b0.z + a0.w * b0.w;
    float p1 = a1.x * b1.x + a1.y * b1.y + a1.z * b1.z + a1.w * b1.w;
    float p2 = a2.x * b2.x + a2.y * b2.y + a2.z * b2.z + a2.w * b2.w;
    float p3 = a3.x * b3.x + a3.y * b3.y + a3.z * b3.z + a3.w * b3.w;
    #pragma unroll
    for (int off = 1; off < 8; off <<= 1) {
        p0 += __shfl_xor_sync(0xffffffffu, p0, off);
        p1 += __shfl_xor_sync(0xffffffffu, p1, off);
        p2 += __shfl_xor_sync(0xffffffffu, p2, off);
        p3 += __shfl_xor_sync(0xffffffffu, p3, off);
    }
    if (sub == 0) {
        unsigned k0 = fkey(p0 * g_rn[s0] * g_rn[d0]);
        unsigned k1 = fkey(p1 * g_rn[s1] * g_rn[d1]);
        unsigned k2 = fkey(p2 * g_rn[s2] * g_rn[d2]);
        unsigned k3 = fkey(p3 * g_rn[s3] * g_rn[d3]);
        g_key[e0]          = k0;
        g_key[e0 + EQ]     = k1;
        g_key[e0 + 2 * EQ] = k2;
        g_key[e0 + 3 * EQ] = k3;
        atomicAdd(&g_h16[k0 >> 16], 1u);
        atomicAdd(&g_h16[k1 >> 16], 1u);
        atomicAdd(&g_h16[k2 >> 16], 1u);
        atomicAdd(&g_h16[k3 >> 16], 1u);
    }
}

// pass-2 histogram: low 16 bits of keys whose top 16 match the selected prefix
__global__ void k_hist2() {
    int i = blockIdx.x * blockDim.x + threadIdx.x;
    if (i >= EE / 4) return;
    unsigned hi = g_prefix >> 16;
    uint4 k = ((const uint4*)g_key)[i];
    if ((k.x >> 16) == hi) atomicAdd(&g_h16[k.x & 0xFFFFu], 1u);
    if ((k.y >> 16) == hi) atomicAdd(&g_h16[k.y & 0xFFFFu], 1u);
    if ((k.z >> 16) == hi) atomicAdd(&g_h16[k.z & 0xFFFFu], 1u);
    if ((k.w >> 16) == hi) atomicAdd(&g_h16[k.w & 0xFFFFu], 1u);
}

// scan 65536 bins with one 1024-thread block (64 bins/thread), find the bucket
// whose cumulative count crosses g_kremain; zero the bins for the next use.
// phase 0: bucket is the top-16 prefix.  phase 1: bucket completes the 32-bit key.
__global__ void k_scan16(int phase) {
    __shared__ unsigned sh[1024];
    int t = threadIdx.x;
    int base = t * 64;
    unsigned s = 0;
    #pragma unroll 8
    for (int i = 0; i < 64; i++) s += g_h16[base + i];
    sh[t] = s;
    __syncthreads();
    for (int off = 1; off < 1024; off <<= 1) {
        unsigned v = (t >= off) ? sh[t - off] : 0u;
        __syncthreads();
        sh[t] += v;
        __syncthreads();
    }
    unsigned incl = sh[t];
    unsigned excl = incl - s;
    unsigned kr = g_kremain;
    if (excl < kr && incl >= kr) {          // exactly one thread
        unsigned run = excl;
        for (int i = 0; i < 64; i++) {
            unsigned c = g_h16[base + i];
            if (run + c >= kr) {
                if (phase == 0) g_prefix = ((unsigned)(base + i)) << 16;
                else            g_prefix |= (unsigned)(base + i);
                g_kremain = kr - run;       // rank within (phase0) / #equals to drop (phase1)
                break;
            }
            run += c;
        }
    }
    #pragma unroll 8
    for (int i = 0; i < 64; i++) g_h16[base + i] = 0;
}

// 8 lanes per edge, 4 edges per group: pruned message scatter via red.v4
// SQ=0 -> scale norm[src], SQ=1 -> norm[src]^2
template <int SQ>
__global__ void k_scatter(const float4* __restrict__ X4, float* __restrict__ Y,
                          const int* __restrict__ src, const int* __restrict__ dst) {
    int gid = blockIdx.x * blockDim.x + threadIdx.x;
    int e0  = gid >> 3;
    int sub = gid & 7;
    int lane   = threadIdx.x & 31;
    int leader = lane & 24;

    unsigned kp = 0;
    if (sub == 0) {
        unsigned T = g_prefix;
        unsigned need_eq = g_kremain;
        #pragma unroll
        for (int j = 0; j < 4; j++) {
            unsigned u = g_key[e0 + j * EQ];
            if (u > T) kp |= (1u << j);
            else if (u == T && atomicAdd(&g_ticket, 1u) >= need_eq) kp |= (1u << j);
        }
    }
    kp = __shfl_sync(0xffffffffu, kp, leader);
    if (kp == 0) return;

    #pragma unroll
    for (int j = 0; j < 4; j++) {
        if (kp & (1u << j)) {
            int e = e0 + j * EQ;
            int s = src[e], d = dst[e];
            float ns = g_norm[s];
            if (SQ) ns *= ns;
            float4 a = X4[s * 8 + sub];
            a.x *= ns; a.y *= ns; a.z *= ns; a.w *= ns;
            float* p = Y + d * DD + sub * 4;
            asm volatile("red.global.add.v4.f32 [%0], {%1, %2, %3, %4};"
                         :: "l"(p), "f"(a.x), "f"(a.y), "f"(a.z), "f"(a.w) : "memory");
        }
    }
}

// out[i,:] = (Y2[i,:] * norm[i]) @ W^T    W is [32,32] row-major
__global__ void k_fc(const float4* __restrict__ Y4, const float* __restrict__ W,
                     float* __restrict__ out) {
    __shared__ float sW[DD * DD];
    int t = threadIdx.x;
    #pragma unroll
    for (int i = 0; i < 4; i++) sW[t + i * 256] = W[t + i * 256];
    __syncthreads();

    int node = blockIdx.x * blockDim.x + t;
    if (node >= NN) return;
    float nrm = g_norm[node];
    float y[DD];
    #pragma unroll
    for (int j = 0; j < 8; j++) {
        float4 v = Y4[node * 8 + j];
        y[j * 4 + 0] = v.x * nrm;
        y[j * 4 + 1] = v.y * nrm;
        y[j * 4 + 2] = v.z * nrm;
        y[j * 4 + 3] = v.w * nrm;
    }
    #pragma unroll
    for (int o = 0; o < DD; o += 4) {
        float4 acc = make_float4(0.f, 0.f, 0.f, 0.f);
        #pragma unroll
        for (int k = 0; k < DD; k++) {
            float yk = y[k];
            acc.x += yk * sW[(o + 0) * DD + k];
            acc.y += yk * sW[(o + 1) * DD + k];
            acc.z += yk * sW[(o + 2) * DD + k];
            acc.w += yk * sW[(o + 3) * DD + k];
        }
        *reinterpret_cast<float4*>(out + node * DD + o) = acc;
    }
}

// ---------------- launch ----------------

extern "C" void kernel_launch(void* const* d_in, const int* in_sizes, int n_in,
                              void* d_out, int out_size) {
    const float* F   = (const float*)d_in[0];
    const float* W   = (const float*)d_in[1];
    const int*   src = (const int*)d_in[2];
    const int*   dst = (const int*)d_in[3];
    float* out = (float*)d_out;

    const float4* F4 = (const float4*)F;

    void* p1; void* p2;
    cudaGetSymbolAddress(&p1, g_Y1);
    cudaGetSymbolAddress(&p2, g_Y2);
    float* Y1 = (float*)p1;
    float* Y2 = (float*)p2;

    const int TB = 256;
    const int gridN  = (NN + TB - 1) / TB;     // 391
    const int gridN8 = (NN * 8) / TB;          // 3125 (exact)
    const int gridE4 = (EQ * 8) / TB;          // 12500 (exact, 4 edges/group)
    const int gridV4 = (EE / 4 + TB - 1) / TB; // 1563 (uint4/int4 domain)

    // init (zero Y1,Y2,deg,h16,scalars) -> degree -> rn+norm
    k_init<<<gridN8, TB>>>();
    k_deg<<<gridV4, TB>>>((const int4*)dst);

    // ---- hop 1 ----
    k_rn<1, 0><<<gridN8, TB>>>(F4);            // rn(F) + deg-norm
    k_cos<<<gridE4, TB>>>(F4, src, dst);       // keys + fused top-16 hist
    k_scan16<<<1, 1024>>>(0);
    k_hist2<<<gridV4, TB>>>();
    k_scan16<<<1, 1024>>>(1);
    k_scatter<0><<<gridE4, TB>>>(F4, Y1, src, dst);

    // ---- hop 2 (cosine scale-invariant; norm folded as norm^2) ----
    k_rn<0, 1><<<gridN8, TB>>>((const float4*)Y1);  // rn(Y1) + selector re-arm
    k_cos<<<gridE4, TB>>>((const float4*)Y1, src, dst);
    k_scan16<<<1, 1024>>>(0);
    k_hist2<<<gridV4, TB>>>();
    k_scan16<<<1, 1024>>>(1);
    k_scatter<1><<<gridE4, TB>>>((const float4*)Y1, Y2, src, dst);

    // ---- final: out = (Y2 * norm) @ W^T ----
    k_fc<<<gridN, TB>>>((const float4*)Y2, W, out);
}

// round 6
// speedup vs baseline: 2.9039x; 2.9039x over previous
#include <cuda_runtime.h>
#include <cstdint>

#define NN 100000
#define EE 1600000
#define EQ 400000          // EE/4 (unroll-4 split)
#define DD 32
#define CUT_K 320000       // int(1600000 * 0.2)
#define EPS 1e-12f

// ---------------- scratch (static device globals; no allocation) ----------------
__device__ float     g_Y1[NN * DD];
__device__ float     g_Y2[NN * DD];
__device__ unsigned  g_key[EE];       // monotone uint key of cosine
__device__ float     g_rn[NN];        // 1 / max(||row||, eps)
__device__ float     g_norm[NN];      // clip(deg,1)^-0.5
__device__ int       g_deg[NN];
__device__ unsigned  g_bins[4096];    // shared accumulation bins (256 used in pass 0)
__device__ unsigned  g_done = 0;      // last-block ticket
__device__ unsigned  g_prefix;        // selected threshold key (built over 3 passes)
__device__ unsigned  g_kremain;       // running rank / final #equal-keys to drop
__device__ unsigned  g_ticket;        // tie-break ticket counter

// monotone float -> uint key (ascending float order == ascending unsigned order)
__device__ __forceinline__ unsigned fkey(float f) {
    unsigned u = __float_as_uint(f);
    return (u & 0x80000000u) ? ~u : (u | 0x80000000u);
}

// ---------------- kernels ----------------

// zero Y1 + Y2 + deg + bins + scalars (grid 3125 x 256 = 800K threads)
__global__ void k_init() {
    int i = blockIdx.x * blockDim.x + threadIdx.x;
    ((float4*)g_Y1)[i] = make_float4(0.f, 0.f, 0.f, 0.f);
    ((float4*)g_Y2)[i] = make_float4(0.f, 0.f, 0.f, 0.f);
    if (i < NN) g_deg[i] = 0;
    if (i < 4096) g_bins[i] = 0;
    if (i == 0) { g_prefix = 0u; g_kremain = CUT_K; g_ticket = 0u; g_done = 0u; }
}

// int4-vectorized degree count
__global__ void k_deg(const int4* __restrict__ dst4) {
    int i = blockIdx.x * blockDim.x + threadIdx.x;
    if (i < EE / 4) {
        int4 d = dst4[i];
        atomicAdd(&g_deg[d.x], 1);
        atomicAdd(&g_deg[d.y], 1);
        atomicAdd(&g_deg[d.z], 1);
        atomicAdd(&g_deg[d.w], 1);
    }
}

// 8 lanes per node: inverse L2 row norm; optionally deg-norm / selector re-arm
template <int DO_NORM, int RESET>
__global__ void k_rn(const float4* __restrict__ X4) {
    int gid  = blockIdx.x * blockDim.x + threadIdx.x;
    int node = gid >> 3;
    int sub  = gid & 7;
    float4 v = X4[node * 8 + sub];
    float s = v.x * v.x + v.y * v.y + v.z * v.z + v.w * v.w;
    s += __shfl_xor_sync(0xffffffffu, s, 1);
    s += __shfl_xor_sync(0xffffffffu, s, 2);
    s += __shfl_xor_sync(0xffffffffu, s, 4);
    if (sub == 0) {
        g_rn[node] = 1.0f / fmaxf(sqrtf(s), EPS);
        if (DO_NORM) {
            int d = g_deg[node];
            if (d < 1) d = 1;
            g_norm[node] = 1.0f / sqrtf((float)d);
        }
    }
    if (RESET && gid == 0) { g_prefix = 0u; g_kremain = CUT_K; g_ticket = 0u; }
}

// 8 lanes per edge, 4 edges per group; keys + fused smem-privatized top-8 hist
// + fused last-block scan (sets g_prefix bits [24:32), updates g_kremain)
__global__ void k_cos(const float4* __restrict__ X4,
                      const int* __restrict__ src, const int* __restrict__ dst) {
    __shared__ unsigned sh[256];
    sh[threadIdx.x] = 0;   // blockDim == 256
    __syncthreads();

    int gid = blockIdx.x * blockDim.x + threadIdx.x;
    int e0  = gid >> 3;
    int sub = gid & 7;

    int s0 = src[e0],          d0 = dst[e0];
    int s1 = src[e0 + EQ],     d1 = dst[e0 + EQ];
    int s2 = src[e0 + 2 * EQ], d2 = dst[e0 + 2 * EQ];
    int s3 = src[e0 + 3 * EQ], d3 = dst[e0 + 3 * EQ];

    float4 a0 = X4[s0 * 8 + sub], b0 = X4[d0 * 8 + sub];
    float4 a1 = X4[s1 * 8 + sub], b1 = X4[d1 * 8 + sub];
    float4 a2 = X4[s2 * 8 + sub], b2 = X4[d2 * 8 + sub];
    float4 a3 = X4[s3 * 8 + sub], b3 = X4[d3 * 8 + sub];

    float p0 = a0.x * b0.x + a0.y * b0.y + a0.z * b0.z + a0.w * b0.w;
    float p1 = a1.x * b1.x + a1.y * b1.y + a1.z * b1.z + a1.w * b1.w;
    float p2 = a2.x * b2.x + a2.y * b2.y + a2.z * b2.z + a2.w * b2.w;
    float p3 = a3.x * b3.x + a3.y * b3.y + a3.z * b3.z + a3.w * b3.w;
    #pragma unroll
    for (int off = 1; off < 8; off <<= 1) {
        p0 += __shfl_xor_sync(0xffffffffu, p0, off);
        p1 += __shfl_xor_sync(0xffffffffu, p1, off);
        p2 += __shfl_xor_sync(0xffffffffu, p2, off);
        p3 += __shfl_xor_sync(0xffffffffu, p3, off);
    }
    if (sub == 0) {
        unsigned k0 = fkey(p0 * g_rn[s0] * g_rn[d0]);
        unsigned k1 = fkey(p1 * g_rn[s1] * g_rn[d1]);
        unsigned k2 = fkey(p2 * g_rn[s2] * g_rn[d2]);
        unsigned k3 = fkey(p3 * g_rn[s3] * g_rn[d3]);
        g_key[e0]          = k0;
        g_key[e0 + EQ]     = k1;
        g_key[e0 + 2 * EQ] = k2;
        g_key[e0 + 3 * EQ] = k3;
        atomicAdd(&sh[k0 >> 24], 1u);
        atomicAdd(&sh[k1 >> 24], 1u);
        atomicAdd(&sh[k2 >> 24], 1u);
        atomicAdd(&sh[k3 >> 24], 1u);
    }
    __syncthreads();
    unsigned c = sh[threadIdx.x];
    if (c) atomicAdd(&g_bins[threadIdx.x], c);

    // ---- last-block: scan 256 bins, select top-8 prefix ----
    __threadfence();
    __syncthreads();
    int last = 0;
    if (threadIdx.x == 0) last = (atomicAdd(&g_done, 1u) == gridDim.x - 1);
    last = __syncthreads_or(last);
    if (!last) return;

    int t = threadIdx.x;
    unsigned cnt = g_bins[t];
    sh[t] = cnt;
    __syncthreads();
    #pragma unroll
    for (int off = 1; off < 256; off <<= 1) {
        unsigned v = (t >= off) ? sh[t - off] : 0u;
        __syncthreads();
        sh[t] += v;
        __syncthreads();
    }
    unsigned incl = sh[t];
    unsigned excl = incl - cnt;
    unsigned kr = g_kremain;
    if (excl < kr && incl >= kr) {        // exactly one thread
        g_prefix = ((unsigned)t) << 24;
        g_kremain = kr - excl;
    }
    g_bins[t] = 0;
    if (t == 0) g_done = 0;
}

// 12-bit radix pass (SHIFT=12 then SHIFT=0), smem-privatized 4096-bin hist
// + fused last-block scan.
template <int SHIFT>
__global__ void k_hs12() {
    __shared__ unsigned sh[4096];
    int t = threadIdx.x;                  // blockDim == 256
    #pragma unroll
    for (int i = 0; i < 16; i++) sh[t + i * 256] = 0;
    __syncthreads();

    unsigned hi = g_prefix >> (SHIFT + 12);
    int stride = gridDim.x * blockDim.x;
    for (int i = blockIdx.x * blockDim.x + t; i < EE / 4; i += stride) {
        uint4 k = ((const uint4*)g_key)[i];
        if ((k.x >> (SHIFT + 12)) == hi) atomicAdd(&sh[(k.x >> SHIFT) & 0xFFFu], 1u);
        if ((k.y >> (SHIFT + 12)) == hi) atomicAdd(&sh[(k.y >> SHIFT) & 0xFFFu], 1u);
        if ((k.z >> (SHIFT + 12)) == hi) atomicAdd(&sh[(k.z >> SHIFT) & 0xFFFu], 1u);
        if ((k.w >> (SHIFT + 12)) == hi) atomicAdd(&sh[(k.w >> SHIFT) & 0xFFFu], 1u);
    }
    __syncthreads();
    #pragma unroll
    for (int i = 0; i < 16; i++) {
        unsigned c = sh[t + i * 256];
        if (c) atomicAdd(&g_bins[t + i * 256], c);
    }

    __threadfence();
    __syncthreads();
    int last = 0;
    if (t == 0) last = (atomicAdd(&g_done, 1u) == gridDim.x - 1);
    last = __syncthreads_or(last);
    if (!last) return;

    // scan 4096 bins: 16 per thread, then block scan of per-thread sums
    unsigned mysum = 0;
    unsigned local[16];
    #pragma unroll
    for (int i = 0; i < 16; i++) { local[i] = g_bins[t * 16 + i]; mysum += local[i]; }
    sh[t] = mysum;
    __syncthreads();
    #pragma unroll
    for (int off = 1; off < 256; off <<= 1) {
        unsigned v = (t >= off) ? sh[t - off] : 0u;
        __syncthreads();
        sh[t] += v;
        __syncthreads();
    }
    unsigned incl = sh[t];
    unsigned excl = incl - mysum;
    unsigned kr = g_kremain;
    if (excl < kr && incl >= kr) {        // exactly one thread
        unsigned run = excl;
        #pragma unroll
        for (int i = 0; i < 16; i++) {
            if (run + local[i] >= kr) {
                g_prefix |= ((unsigned)(t * 16 + i)) << SHIFT;
                g_kremain = kr - run;
                break;
            }
            run += local[i];
        }
    }
    #pragma unroll
    for (int i = 0; i < 16; i++) g_bins[t * 16 + i] = 0;
    if (t == 0) g_done = 0;
}

// 8 lanes per edge, 4 edges per group: pruned message scatter via red.v4
// SQ=0 -> scale norm[src], SQ=1 -> norm[src]^2
template <int SQ>
__global__ void k_scatter(const float4* __restrict__ X4, float* __restrict__ Y,
                          const int* __restrict__ src, const int* __restrict__ dst) {
    int gid = blockIdx.x * blockDim.x + threadIdx.x;
    int e0  = gid >> 3;
    int sub = gid & 7;
    int lane   = threadIdx.x & 31;
    int leader = lane & 24;

    unsigned kp = 0;
    if (sub == 0) {
        unsigned T = g_prefix;
        unsigned need_eq = g_kremain;
        #pragma unroll
        for (int j = 0; j < 4; j++) {
            unsigned u = g_key[e0 + j * EQ];
            if (u > T) kp |= (1u << j);
            else if (u == T && atomicAdd(&g_ticket, 1u) >= need_eq) kp |= (1u << j);
        }
    }
    kp = __shfl_sync(0xffffffffu, kp, leader);
    if (kp == 0) return;

    #pragma unroll
    for (int j = 0; j < 4; j++) {
        if (kp & (1u << j)) {
            int e = e0 + j * EQ;
            int s = src[e], d = dst[e];
            float ns = g_norm[s];
            if (SQ) ns *= ns;
            float4 a = X4[s * 8 + sub];
            a.x *= ns; a.y *= ns; a.z *= ns; a.w *= ns;
            float* p = Y + d * DD + sub * 4;
            asm volatile("red.global.add.v4.f32 [%0], {%1, %2, %3, %4};"
                         :: "l"(p), "f"(a.x), "f"(a.y), "f"(a.z), "f"(a.w) : "memory");
        }
    }
}

// out[i,:] = (Y2[i,:] * norm[i]) @ W^T    W is [32,32] row-major
__global__ void k_fc(const float4* __restrict__ Y4, const float* __restrict__ W,
                     float* __restrict__ out) {
    __shared__ float sW[DD * DD];
    int t = threadIdx.x;
    #pragma unroll
    for (int i = 0; i < 4; i++) sW[t + i * 256] = W[t + i * 256];
    __syncthreads();

    int node = blockIdx.x * blockDim.x + t;
    if (node >= NN) return;
    float nrm = g_norm[node];
    float y[DD];
    #pragma unroll
    for (int j = 0; j < 8; j++) {
        float4 v = Y4[node * 8 + j];
        y[j * 4 + 0] = v.x * nrm;
        y[j * 4 + 1] = v.y * nrm;
        y[j * 4 + 2] = v.z * nrm;
        y[j * 4 + 3] = v.w * nrm;
    }
    #pragma unroll
    for (int o = 0; o < DD; o += 4) {
        float4 acc = make_float4(0.f, 0.f, 0.f, 0.f);
        #pragma unroll
        for (int k = 0; k < DD; k++) {
            float yk = y[k];
            acc.x += yk * sW[(o + 0) * DD + k];
            acc.y += yk * sW[(o + 1) * DD + k];
            acc.z += yk * sW[(o + 2) * DD + k];
            acc.w += yk * sW[(o + 3) * DD + k];
        }
        *reinterpret_cast<float4*>(out + node * DD + o) = acc;
    }
}

// ---------------- launch ----------------

extern "C" void kernel_launch(void* const* d_in, const int* in_sizes, int n_in,
                              void* d_out, int out_size) {
    const float* F   = (const float*)d_in[0];
    const float* W   = (const float*)d_in[1];
    const int*   src = (const int*)d_in[2];
    const int*   dst = (const int*)d_in[3];
    float* out = (float*)d_out;

    const float4* F4 = (const float4*)F;

    void* p1; void* p2;
    cudaGetSymbolAddress(&p1, g_Y1);
    cudaGetSymbolAddress(&p2, g_Y2);
    float* Y1 = (float*)p1;
    float* Y2 = (float*)p2;

    const int TB = 256;
    const int gridN  = (NN + TB - 1) / TB;     // 391
    const int gridN8 = (NN * 8) / TB;          // 3125 (exact)
    const int gridE4 = (EQ * 8) / TB;          // 12500 (exact, 4 edges/group)
    const int gridV4 = (EE / 4 + TB - 1) / TB; // 1563 (uint4/int4 domain)
    const int gridHS = 1184;                   // 8 blocks/SM for hist passes

    k_init<<<gridN8, TB>>>();
    k_deg<<<gridV4, TB>>>((const int4*)dst);

    // ---- hop 1 ----
    k_rn<1, 0><<<gridN8, TB>>>(F4);            // rn(F) + deg-norm
    k_cos<<<gridE4, TB>>>(F4, src, dst);       // keys + pass0 hist + scan
    k_hs12<12><<<gridHS, TB>>>();              // bits [12:24)
    k_hs12<0><<<gridHS, TB>>>();               // bits [0:12)
    k_scatter<0><<<gridE4, TB>>>(F4, Y1, src, dst);

    // ---- hop 2 (cosine scale-invariant; norm folded as norm^2) ----
    k_rn<0, 1><<<gridN8, TB>>>((const float4*)Y1);  // rn(Y1) + selector re-arm
    k_cos<<<gridE4, TB>>>((const float4*)Y1, src, dst);
    k_hs12<12><<<gridHS, TB>>>();
    k_hs12<0><<<gridHS, TB>>>();
    k_scatter<1><<<gridE4, TB>>>((const float4*)Y1, Y2, src, dst);

    // ---- final: out = (Y2 * norm) @ W^T ----
    k_fc<<<gridN, TB>>>((const float4*)Y2, W, out);
}

// round 9
// speedup vs baseline: 3.2755x; 1.1279x over previous
#include <cuda_runtime.h>
#include <cstdint>

#define NN 100000
#define EE 1600000
#define EG 400000          // EE/4 (4 contiguous edges per 8-lane group)
#define DD 32
#define CUT_K 320000       // int(1600000 * 0.2)
#define EPS 1e-12f

// ---------------- scratch (static device globals; no allocation) ----------------
__device__ float     g_Y1[NN * DD];
__device__ float     g_Y2[NN * DD];
__device__ unsigned  g_key[EE];       // monotone uint key of cosine
__device__ float     g_rn[NN];        // 1 / max(||row||, eps)
__device__ float     g_norm[NN];      // clip(deg,1)^-0.5
__device__ int       g_deg[NN];
__device__ unsigned  g_bins[4096];    // accumulation bins (256 used in pass 0)
__device__ unsigned  g_done = 0;      // last-block ticket
__device__ unsigned  g_prefix;        // selected threshold key (built over 3 passes)
__device__ unsigned  g_kremain;       // running rank / final #equal-keys to drop
__device__ unsigned  g_ticket;        // tie-break ticket counter

// monotone float -> uint key
__device__ __forceinline__ unsigned fkey(float f) {
    unsigned u = __float_as_uint(f);
    return (u & 0x80000000u) ? ~u : (u | 0x80000000u);
}

// gpu-scope acq_rel ticket: release chains block's prior (syncthreads-ordered)
// global atomics; acquire makes g_bins visible to the last block. No CCTL.IVALL
// storm from per-block __threadfence().
__device__ __forceinline__ unsigned ticket_acqrel(unsigned* p) {
    unsigned old;
    asm volatile("atom.add.acq_rel.gpu.global.u32 %0, [%1], %2;"
                 : "=r"(old) : "l"(p), "r"(1u) : "memory");
    return old;
}

// ---------------- kernels ----------------

// zero Y1 + Y2 + deg + bins + scalars (grid 3125 x 256)
__global__ void k_init() {
    int i = blockIdx.x * blockDim.x + threadIdx.x;
    ((float4*)g_Y1)[i] = make_float4(0.f, 0.f, 0.f, 0.f);
    ((float4*)g_Y2)[i] = make_float4(0.f, 0.f, 0.f, 0.f);
    if (i < NN) g_deg[i] = 0;
    if (i < 4096) g_bins[i] = 0;
    if (i == 0) { g_prefix = 0u; g_kremain = CUT_K; g_ticket = 0u; g_done = 0u; }
}

__global__ void k_deg(const int4* __restrict__ dst4) {
    int i = blockIdx.x * blockDim.x + threadIdx.x;
    if (i < EE / 4) {
        int4 d = dst4[i];
        atomicAdd(&g_deg[d.x], 1);
        atomicAdd(&g_deg[d.y], 1);
        atomicAdd(&g_deg[d.z], 1);
        atomicAdd(&g_deg[d.w], 1);
    }
}

// 8 lanes per node: inverse L2 row norm; optionally deg-norm / selector re-arm
template <int DO_NORM, int RESET>
__global__ void k_rn(const float4* __restrict__ X4) {
    int gid  = blockIdx.x * blockDim.x + threadIdx.x;
    int node = gid >> 3;
    int sub  = gid & 7;
    float4 v = X4[node * 8 + sub];
    float s = v.x * v.x + v.y * v.y + v.z * v.z + v.w * v.w;
    s += __shfl_xor_sync(0xffffffffu, s, 1);
    s += __shfl_xor_sync(0xffffffffu, s, 2);
    s += __shfl_xor_sync(0xffffffffu, s, 4);
    if (sub == 0) {
        g_rn[node] = 1.0f / fmaxf(sqrtf(s), EPS);
        if (DO_NORM) {
            int d = g_deg[node];
            if (d < 1) d = 1;
            g_norm[node] = 1.0f / sqrtf((float)d);
        }
    }
    if (RESET && gid == 0) { g_prefix = 0u; g_kremain = CUT_K; g_ticket = 0u; }
}

// 8 lanes x 4 contiguous edges per group; keys + smem top-8 hist + last-block scan
__global__ void __launch_bounds__(256) k_cos(const float4* __restrict__ X4,
                                             const int4* __restrict__ src4,
                                             const int4* __restrict__ dst4) {
    __shared__ unsigned sh[256];
    sh[threadIdx.x] = 0;
    __syncthreads();

    int gid = blockIdx.x * blockDim.x + threadIdx.x;
    int g   = gid >> 3;            // group id: edges [4g, 4g+4)
    int sub = gid & 7;

    int4 S = src4[g];              // broadcast within group
    int4 D = dst4[g];

    float4 a0 = X4[S.x * 8 + sub], b0 = X4[D.x * 8 + sub];
    float4 a1 = X4[S.y * 8 + sub], b1 = X4[D.y * 8 + sub];
    float4 a2 = X4[S.z * 8 + sub], b2 = X4[D.z * 8 + sub];
    float4 a3 = X4[S.w * 8 + sub], b3 = X4[D.w * 8 + sub];

    float p0 = a0.x * b0.x + a0.y * b0.y + a0.z * b0.z + a0.w * b0.w;
    float p1 = a1.x * b1.x + a1.y * b1.y + a1.z * b1.z + a1.w * b1.w;
    float p2 = a2.x * b2.x + a2.y * b2.y + a2.z * b2.z + a2.w * b2.w;
    float p3 = a3.x * b3.x + a3.y * b3.y + a3.z * b3.z + a3.w * b3.w;
    #pragma unroll
    for (int off = 1; off < 8; off <<= 1) {
        p0 += __shfl_xor_sync(0xffffffffu, p0, off);
        p1 += __shfl_xor_sync(0xffffffffu, p1, off);
        p2 += __shfl_xor_sync(0xffffffffu, p2, off);
        p3 += __shfl_xor_sync(0xffffffffu, p3, off);
    }
    if (sub == 0) {
        uint4 k;
        k.x = fkey(p0 * g_rn[S.x] * g_rn[D.x]);
        k.y = fkey(p1 * g_rn[S.y] * g_rn[D.y]);
        k.z = fkey(p2 * g_rn[S.z] * g_rn[D.z]);
        k.w = fkey(p3 * g_rn[S.w] * g_rn[D.w]);
        ((uint4*)g_key)[g] = k;
        atomicAdd(&sh[k.x >> 24], 1u);
        atomicAdd(&sh[k.y >> 24], 1u);
        atomicAdd(&sh[k.z >> 24], 1u);
        atomicAdd(&sh[k.w >> 24], 1u);
    }
    __syncthreads();
    unsigned c = sh[threadIdx.x];
    if (c) atomicAdd(&g_bins[threadIdx.x], c);
    __syncthreads();

    // ---- last-block: scan 256 bins, select top-8 prefix ----
    int last = 0;
    if (threadIdx.x == 0) last = (ticket_acqrel(&g_done) == gridDim.x - 1);
    last = __syncthreads_or(last);
    if (!last) return;

    int t = threadIdx.x;
    unsigned cnt = g_bins[t];
    sh[t] = cnt;
    __syncthreads();
    #pragma unroll
    for (int off = 1; off < 256; off <<= 1) {
        unsigned v = (t >= off) ? sh[t - off] : 0u;
        __syncthreads();
        sh[t] += v;
        __syncthreads();
    }
    unsigned incl = sh[t];
    unsigned excl = incl - cnt;
    unsigned kr = g_kremain;
    if (excl < kr && incl >= kr) {
        g_prefix = ((unsigned)t) << 24;
        g_kremain = kr - excl;
    }
    g_bins[t] = 0;
    if (t == 0) g_done = 0;
}

// 12-bit radix pass (SHIFT=12 then 0): smem 4096-bin hist + last-block scan
template <int SHIFT>
__global__ void __launch_bounds__(256) k_hs12() {
    __shared__ unsigned sh[4096];
    int t = threadIdx.x;
    #pragma unroll
    for (int i = 0; i < 16; i++) sh[t + i * 256] = 0;
    __syncthreads();

    unsigned hi = g_prefix >> (SHIFT + 12);
    int stride = gridDim.x * blockDim.x;
    for (int i = blockIdx.x * blockDim.x + t; i < EE / 4; i += stride) {
        uint4 k = ((const uint4*)g_key)[i];
        if ((k.x >> (SHIFT + 12)) == hi) atomicAdd(&sh[(k.x >> SHIFT) & 0xFFFu], 1u);
        if ((k.y >> (SHIFT + 12)) == hi) atomicAdd(&sh[(k.y >> SHIFT) & 0xFFFu], 1u);
        if ((k.z >> (SHIFT + 12)) == hi) atomicAdd(&sh[(k.z >> SHIFT) & 0xFFFu], 1u);
        if ((k.w >> (SHIFT + 12)) == hi) atomicAdd(&sh[(k.w >> SHIFT) & 0xFFFu], 1u);
    }
    __syncthreads();
    #pragma unroll
    for (int i = 0; i < 16; i++) {
        unsigned c = sh[t + i * 256];
        if (c) atomicAdd(&g_bins[t + i * 256], c);
    }
    __syncthreads();

    int last = 0;
    if (t == 0) last = (ticket_acqrel(&g_done) == gridDim.x - 1);
    last = __syncthreads_or(last);
    if (!last) return;

    unsigned mysum = 0;
    unsigned local[16];
    #pragma unroll
    for (int i = 0; i < 16; i++) { local[i] = g_bins[t * 16 + i]; mysum += local[i]; }
    sh[t] = mysum;
    __syncthreads();
    #pragma unroll
    for (int off = 1; off < 256; off <<= 1) {
        unsigned v = (t >= off) ? sh[t - off] : 0u;
        __syncthreads();
        sh[t] += v;
        __syncthreads();
    }
    unsigned incl = sh[t];
    unsigned excl = incl - mysum;
    unsigned kr = g_kremain;
    if (excl < kr && incl >= kr) {
        unsigned run = excl;
        #pragma unroll
        for (int i = 0; i < 16; i++) {
            if (run + local[i] >= kr) {
                g_prefix |= ((unsigned)(t * 16 + i)) << SHIFT;
                g_kremain = kr - run;
                break;
            }
            run += local[i];
        }
    }
    #pragma unroll
    for (int i = 0; i < 16; i++) g_bins[t * 16 + i] = 0;
    if (t == 0) g_done = 0;
}

// 8 lanes x 4 contiguous edges per group: pruned scatter via red.v4
// SQ=0 -> scale norm[src], SQ=1 -> norm[src]^2
template <int SQ>
__global__ void __launch_bounds__(256) k_scatter(const float4* __restrict__ X4,
                                                 float* __restrict__ Y,
                                                 const int4* __restrict__ src4,
                                                 const int4* __restrict__ dst4) {
    int gid = blockIdx.x * blockDim.x + threadIdx.x;
    int g   = gid >> 3;
    int sub = gid & 7;
    int lane   = threadIdx.x & 31;
    int leader = lane & 24;

    unsigned kp = 0;
    if (sub == 0) {
        unsigned T = g_prefix;
        unsigned need_eq = g_kremain;
        uint4 k = ((const uint4*)g_key)[g];
        unsigned u[4] = {k.x, k.y, k.z, k.w};
        #pragma unroll
        for (int j = 0; j < 4; j++) {
            if (u[j] > T) kp |= (1u << j);
            else if (u[j] == T && atomicAdd(&g_ticket, 1u) >= need_eq) kp |= (1u << j);
        }
    }
    kp = __shfl_sync(0xffffffffu, kp, leader);
    if (kp == 0) return;

    int4 S = src4[g];
    int4 D = dst4[g];
    int s[4] = {S.x, S.y, S.z, S.w};
    int d[4] = {D.x, D.y, D.z, D.w};

    #pragma unroll
    for (int j = 0; j < 4; j++) {
        if (kp & (1u << j)) {
            float ns = g_norm[s[j]];
            if (SQ) ns *= ns;
            float4 a = X4[s[j] * 8 + sub];
            a.x *= ns; a.y *= ns; a.z *= ns; a.w *= ns;
            float* p = Y + d[j] * DD + sub * 4;
            asm volatile("red.global.add.v4.f32 [%0], {%1, %2, %3, %4};"
                         :: "l"(p), "f"(a.x), "f"(a.y), "f"(a.z), "f"(a.w) : "memory");
        }
    }
}

// out[i,:] = (Y2[i,:] * norm[i]) @ W^T    W is [32,32] row-major
__global__ void k_fc(const float4* __restrict__ Y4, const float* __restrict__ W,
                     float* __restrict__ out) {
    __shared__ float sW[DD * DD];
    int t = threadIdx.x;
    #pragma unroll
    for (int i = 0; i < 4; i++) sW[t + i * 256] = W[t + i * 256];
    __syncthreads();

    int node = blockIdx.x * blockDim.x + t;
    if (node >= NN) return;
    float nrm = g_norm[node];
    float y[DD];
    #pragma unroll
    for (int j = 0; j < 8; j++) {
        float4 v = Y4[node * 8 + j];
        y[j * 4 + 0] = v.x * nrm;
        y[j * 4 + 1] = v.y * nrm;
        y[j * 4 + 2] = v.z * nrm;
        y[j * 4 + 3] = v.w * nrm;
    }
    #pragma unroll
    for (int o = 0; o < DD; o += 4) {
        float4 acc = make_float4(0.f, 0.f, 0.f, 0.f);
        #pragma unroll
        for (int k = 0; k < DD; k++) {
            float yk = y[k];
            acc.x += yk * sW[(o + 0) * DD + k];
            acc.y += yk * sW[(o + 1) * DD + k];
            acc.z += yk * sW[(o + 2) * DD + k];
            acc.w += yk * sW[(o + 3) * DD + k];
        }
        *reinterpret_cast<float4*>(out + node * DD + o) = acc;
    }
}

// ---------------- launch ----------------

extern "C" void kernel_launch(void* const* d_in, const int* in_sizes, int n_in,
                              void* d_out, int out_size) {
    const float* F   = (const float*)d_in[0];
    const float* W   = (const float*)d_in[1];
    const int*   src = (const int*)d_in[2];
    const int*   dst = (const int*)d_in[3];
    float* out = (float*)d_out;

    const float4* F4  = (const float4*)F;
    const int4* src4  = (const int4*)src;
    const int4* dst4  = (const int4*)dst;

    void* p1; void* p2;
    cudaGetSymbolAddress(&p1, g_Y1);
    cudaGetSymbolAddress(&p2, g_Y2);
    float* Y1 = (float*)p1;
    float* Y2 = (float*)p2;

    const int TB = 256;
    const int gridN  = (NN + TB - 1) / TB;     // 391
    const int gridN8 = (NN * 8) / TB;          // 3125 (exact)
    const int gridE4 = (EG * 8) / TB;          // 12500 (exact)
    const int gridV4 = (EE / 4 + TB - 1) / TB; // 1563
    const int gridHS = 1184;

    k_init<<<gridN8, TB>>>();
    k_deg<<<gridV4, TB>>>(dst4);

    // ---- hop 1 ----
    k_rn<1, 0><<<gridN8, TB>>>(F4);            // rn(F) + deg-norm
    k_cos<<<gridE4, TB>>>(F4, src4, dst4);     // keys + pass0 hist + scan
    k_hs12<12><<<gridHS, TB>>>();              // bits [12:24)
    k_hs12<0><<<gridHS, TB>>>();               // bits [0:12)
    k_scatter<0><<<gridE4, TB>>>(F4, Y1, src4, dst4);

    // ---- hop 2 (cosine scale-invariant; norm folded as norm^2) ----
    k_rn<0, 1><<<gridN8, TB>>>((const float4*)Y1);  // rn(Y1) + selector re-arm
    k_cos<<<gridE4, TB>>>((const float4*)Y1, src4, dst4);
    k_hs12<12><<<gridHS, TB>>>();
    k_hs12<0><<<gridHS, TB>>>();
    k_scatter<1><<<gridE4, TB>>>((const float4*)Y1, Y2, src4, dst4);

    // ---- final: out = (Y2 * norm) @ W^T ----
    k_fc<<<gridN, TB>>>((const float4*)Y2, W, out);
}

// round 10
// speedup vs baseline: 3.4526x; 1.0541x over previous
#include <cuda_runtime.h>
#include <cstdint>

#define NN 100000
#define EE 1600000
#define EG 400000          // EE/4 (4 contiguous edges per 8-lane group)
#define DD 32
#define CUT_K 320000       // int(1600000 * 0.2)
#define EPS 1e-12f

// ---------------- scratch (static device globals; no allocation) ----------------
__device__ float     g_Y1[NN * DD];
__device__ float     g_Y2[NN * DD];
__device__ float     g_NH[NN * DD];   // L2-normalized rows of current hop input
__device__ unsigned  g_key[EE];       // monotone uint key of cosine
__device__ float     g_norm[NN];      // clip(deg,1)^-0.5
__device__ int       g_deg[NN];
__device__ unsigned  g_bins[4096];    // accumulation bins (256 used in pass 0)
__device__ unsigned  g_done = 0;      // last-block ticket
__device__ unsigned  g_prefix;        // selected threshold key (built over 3 passes)
__device__ unsigned  g_kremain;       // running rank / final #equal-keys to drop
__device__ unsigned  g_ticket;        // tie-break ticket counter

// monotone float -> uint key
__device__ __forceinline__ unsigned fkey(float f) {
    unsigned u = __float_as_uint(f);
    return (u & 0x80000000u) ? ~u : (u | 0x80000000u);
}

// gpu-scope acq_rel ticket (no CCTL.IVALL L1 flush, unlike __threadfence)
__device__ __forceinline__ unsigned ticket_acqrel(unsigned* p) {
    unsigned old;
    asm volatile("atom.add.acq_rel.gpu.global.u32 %0, [%1], %2;"
                 : "=r"(old) : "l"(p), "r"(1u) : "memory");
    return old;
}

// ---------------- kernels ----------------

// zero Y1 + Y2 + deg + bins + scalars (grid 3125 x 256)
__global__ void k_init() {
    int i = blockIdx.x * blockDim.x + threadIdx.x;
    ((float4*)g_Y1)[i] = make_float4(0.f, 0.f, 0.f, 0.f);
    ((float4*)g_Y2)[i] = make_float4(0.f, 0.f, 0.f, 0.f);
    if (i < NN) g_deg[i] = 0;
    if (i < 4096) g_bins[i] = 0;
    if (i == 0) { g_prefix = 0u; g_kremain = CUT_K; g_ticket = 0u; g_done = 0u; }
}

__global__ void k_deg(const int4* __restrict__ dst4) {
    int i = blockIdx.x * blockDim.x + threadIdx.x;
    if (i < EE / 4) {
        int4 d = dst4[i];
        atomicAdd(&g_deg[d.x], 1);
        atomicAdd(&g_deg[d.y], 1);
        atomicAdd(&g_deg[d.z], 1);
        atomicAdd(&g_deg[d.w], 1);
    }
}

// 8 lanes per node: write normalized row NH = X*rn; optionally deg-norm / re-arm
template <int DO_NORM, int RESET>
__global__ void k_prep(const float4* __restrict__ X4) {
    int gid  = blockIdx.x * blockDim.x + threadIdx.x;
    int node = gid >> 3;
    int sub  = gid & 7;
    float4 v = X4[node * 8 + sub];
    float s = v.x * v.x + v.y * v.y + v.z * v.z + v.w * v.w;
    s += __shfl_xor_sync(0xffffffffu, s, 1);
    s += __shfl_xor_sync(0xffffffffu, s, 2);
    s += __shfl_xor_sync(0xffffffffu, s, 4);   // all 8 lanes hold full sum
    float rn = 1.0f / fmaxf(sqrtf(s), EPS);
    float4 nh = make_float4(v.x * rn, v.y * rn, v.z * rn, v.w * rn);
    ((float4*)g_NH)[node * 8 + sub] = nh;
    if (sub == 0 && DO_NORM) {
        int d = g_deg[node];
        if (d < 1) d = 1;
        g_norm[node] = 1.0f / sqrtf((float)d);
    }
    if (RESET && gid == 0) { g_prefix = 0u; g_kremain = CUT_K; g_ticket = 0u; }
}

// 8 lanes x 4 contiguous edges per group; gathers NH rows (L2-only),
// keys + smem top-8 hist + last-block scan
__global__ void __launch_bounds__(256) k_cos(const int4* __restrict__ src4,
                                             const int4* __restrict__ dst4) {
    __shared__ unsigned sh[256];
    sh[threadIdx.x] = 0;
    __syncthreads();

    int gid = blockIdx.x * blockDim.x + threadIdx.x;
    int g   = gid >> 3;            // group id: edges [4g, 4g+4)
    int sub = gid & 7;

    int4 S = __ldcg(&src4[g]);
    int4 D = __ldcg(&dst4[g]);
    const float4* NH4 = (const float4*)g_NH;

    float4 a0 = __ldcg(&NH4[S.x * 8 + sub]), b0 = __ldcg(&NH4[D.x * 8 + sub]);
    float4 a1 = __ldcg(&NH4[S.y * 8 + sub]), b1 = __ldcg(&NH4[D.y * 8 + sub]);
    float4 a2 = __ldcg(&NH4[S.z * 8 + sub]), b2 = __ldcg(&NH4[D.z * 8 + sub]);
    float4 a3 = __ldcg(&NH4[S.w * 8 + sub]), b3 = __ldcg(&NH4[D.w * 8 + sub]);

    float p0 = a0.x * b0.x + a0.y * b0.y + a0.z * b0.z + a0.w * b0.w;
    float p1 = a1.x * b1.x + a1.y * b1.y + a1.z * b1.z + a1.w * b1.w;
    float p2 = a2.x * b2.x + a2.y * b2.y + a2.z * b2.z + a2.w * b2.w;
    float p3 = a3.x * b3.x + a3.y * b3.y + a3.z * b3.z + a3.w * b3.w;
    #pragma unroll
    for (int off = 1; off < 8; off <<= 1) {
        p0 += __shfl_xor_sync(0xffffffffu, p0, off);
        p1 += __shfl_xor_sync(0xffffffffu, p1, off);
        p2 += __shfl_xor_sync(0xffffffffu, p2, off);
        p3 += __shfl_xor_sync(0xffffffffu, p3, off);
    }
    if (sub == 0) {
        uint4 k;
        k.x = fkey(p0);
        k.y = fkey(p1);
        k.z = fkey(p2);
        k.w = fkey(p3);
        ((uint4*)g_key)[g] = k;
        atomicAdd(&sh[k.x >> 24], 1u);
        atomicAdd(&sh[k.y >> 24], 1u);
        atomicAdd(&sh[k.z >> 24], 1u);
        atomicAdd(&sh[k.w >> 24], 1u);
    }
    __syncthreads();
    unsigned c = sh[threadIdx.x];
    if (c) atomicAdd(&g_bins[threadIdx.x], c);
    __syncthreads();

    // ---- last-block: scan 256 bins, select top-8 prefix ----
    int last = 0;
    if (threadIdx.x == 0) last = (ticket_acqrel(&g_done) == gridDim.x - 1);
    last = __syncthreads_or(last);
    if (!last) return;

    int t = threadIdx.x;
    unsigned cnt = g_bins[t];
    sh[t] = cnt;
    __syncthreads();
    #pragma unroll
    for (int off = 1; off < 256; off <<= 1) {
        unsigned v = (t >= off) ? sh[t - off] : 0u;
        __syncthreads();
        sh[t] += v;
        __syncthreads();
    }
    unsigned incl = sh[t];
    unsigned excl = incl - cnt;
    unsigned kr = g_kremain;
    if (excl < kr && incl >= kr) {
        g_prefix = ((unsigned)t) << 24;
        g_kremain = kr - excl;
    }
    g_bins[t] = 0;
    if (t == 0) g_done = 0;
}

// 12-bit radix pass (SHIFT=12 then 0): smem 4096-bin hist + last-block scan
template <int SHIFT>
__global__ void __launch_bounds__(256) k_hs12() {
    __shared__ unsigned sh[4096];
    int t = threadIdx.x;
    #pragma unroll
    for (int i = 0; i < 16; i++) sh[t + i * 256] = 0;
    __syncthreads();

    unsigned hi = g_prefix >> (SHIFT + 12);
    int stride = gridDim.x * blockDim.x;
    for (int i = blockIdx.x * blockDim.x + t; i < EE / 4; i += stride) {
        uint4 k = __ldcg(&((const uint4*)g_key)[i]);
        if ((k.x >> (SHIFT + 12)) == hi) atomicAdd(&sh[(k.x >> SHIFT) & 0xFFFu], 1u);
        if ((k.y >> (SHIFT + 12)) == hi) atomicAdd(&sh[(k.y >> SHIFT) & 0xFFFu], 1u);
        if ((k.z >> (SHIFT + 12)) == hi) atomicAdd(&sh[(k.z >> SHIFT) & 0xFFFu], 1u);
        if ((k.w >> (SHIFT + 12)) == hi) atomicAdd(&sh[(k.w >> SHIFT) & 0xFFFu], 1u);
    }
    __syncthreads();
    #pragma unroll
    for (int i = 0; i < 16; i++) {
        unsigned c = sh[t + i * 256];
        if (c) atomicAdd(&g_bins[t + i * 256], c);
    }
    __syncthreads();

    int last = 0;
    if (t == 0) last = (ticket_acqrel(&g_done) == gridDim.x - 1);
    last = __syncthreads_or(last);
    if (!last) return;

    unsigned mysum = 0;
    unsigned local[16];
    #pragma unroll
    for (int i = 0; i < 16; i++) { local[i] = g_bins[t * 16 + i]; mysum += local[i]; }
    sh[t] = mysum;
    __syncthreads();
    #pragma unroll
    for (int off = 1; off < 256; off <<= 1) {
        unsigned v = (t >= off) ? sh[t - off] : 0u;
        __syncthreads();
        sh[t] += v;
        __syncthreads();
    }
    unsigned incl = sh[t];
    unsigned excl = incl - mysum;
    unsigned kr = g_kremain;
    if (excl < kr && incl >= kr) {
        unsigned run = excl;
        #pragma unroll
        for (int i = 0; i < 16; i++) {
            if (run + local[i] >= kr) {
                g_prefix |= ((unsigned)(t * 16 + i)) << SHIFT;
                g_kremain = kr - run;
                break;
            }
            run += local[i];
        }
    }
    #pragma unroll
    for (int i = 0; i < 16; i++) g_bins[t * 16 + i] = 0;
    if (t == 0) g_done = 0;
}

// 8 lanes x 4 contiguous edges per group: pruned scatter via red.v4
// SQ=0 -> scale norm[src], SQ=1 -> norm[src]^2
template <int SQ>
__global__ void __launch_bounds__(256) k_scatter(const float4* __restrict__ X4,
                                                 float* __restrict__ Y,
                                                 const int4* __restrict__ src4,
                                                 const int4* __restrict__ dst4) {
    int gid = blockIdx.x * blockDim.x + threadIdx.x;
    int g   = gid >> 3;
    int sub = gid & 7;
    int lane   = threadIdx.x & 31;
    int leader = lane & 24;

    unsigned kp = 0;
    if (sub == 0) {
        unsigned T = g_prefix;
        unsigned need_eq = g_kremain;
        uint4 k = __ldcg(&((const uint4*)g_key)[g]);
        unsigned u[4] = {k.x, k.y, k.z, k.w};
        #pragma unroll
        for (int j = 0; j < 4; j++) {
            if (u[j] > T) kp |= (1u << j);
            else if (u[j] == T && atomicAdd(&g_ticket, 1u) >= need_eq) kp |= (1u << j);
        }
    }
    kp = __shfl_sync(0xffffffffu, kp, leader);
    if (kp == 0) return;

    int4 S = __ldcg(&src4[g]);
    int4 D = __ldcg(&dst4[g]);
    int s[4] = {S.x, S.y, S.z, S.w};
    int d[4] = {D.x, D.y, D.z, D.w};

    #pragma unroll
    for (int j = 0; j < 4; j++) {
        if (kp & (1u << j)) {
            float ns = g_norm[s[j]];
            if (SQ) ns *= ns;
            float4 a = __ldcg(&X4[s[j] * 8 + sub]);
            a.x *= ns; a.y *= ns; a.z *= ns; a.w *= ns;
            float* p = Y + d[j] * DD + sub * 4;
            asm volatile("red.global.add.v4.f32 [%0], {%1, %2, %3, %4};"
                         :: "l"(p), "f"(a.x), "f"(a.y), "f"(a.z), "f"(a.w) : "memory");
        }
    }
}

// out[i,:] = (Y2[i,:] * norm[i]) @ W^T    W is [32,32] row-major
__global__ void k_fc(const float4* __restrict__ Y4, const float* __restrict__ W,
                     float* __restrict__ out) {
    __shared__ float sW[DD * DD];
    int t = threadIdx.x;
    #pragma unroll
    for (int i = 0; i < 4; i++) sW[t + i * 256] = W[t + i * 256];
    __syncthreads();

    int node = blockIdx.x * blockDim.x + t;
    if (node >= NN) return;
    float nrm = g_norm[node];
    float y[DD];
    #pragma unroll
    for (int j = 0; j < 8; j++) {
        float4 v = Y4[node * 8 + j];
        y[j * 4 + 0] = v.x * nrm;
        y[j * 4 + 1] = v.y * nrm;
        y[j * 4 + 2] = v.z * nrm;
        y[j * 4 + 3] = v.w * nrm;
    }
    #pragma unroll
    for (int o = 0; o < DD; o += 4) {
        float4 acc = make_float4(0.f, 0.f, 0.f, 0.f);
        #pragma unroll
        for (int k = 0; k < DD; k++) {
            float yk = y[k];
            acc.x += yk * sW[(o + 0) * DD + k];
            acc.y += yk * sW[(o + 1) * DD + k];
            acc.z += yk * sW[(o + 2) * DD + k];
            acc.w += yk * sW[(o + 3) * DD + k];
        }
        *reinterpret_cast<float4*>(out + node * DD + o) = acc;
    }
}

// ---------------- launch ----------------

extern "C" void kernel_launch(void* const* d_in, const int* in_sizes, int n_in,
                              void* d_out, int out_size) {
    const float* F   = (const float*)d_in[0];
    const float* W   = (const float*)d_in[1];
    const int*   src = (const int*)d_in[2];
    const int*   dst = (const int*)d_in[3];
    float* out = (float*)d_out;

    const float4* F4  = (const float4*)F;
    const int4* src4  = (const int4*)src;
    const int4* dst4  = (const int4*)dst;

    void* p1; void* p2;
    cudaGetSymbolAddress(&p1, g_Y1);
    cudaGetSymbolAddress(&p2, g_Y2);
    float* Y1 = (float*)p1;
    float* Y2 = (float*)p2;

    const int TB = 256;
    const int gridN  = (NN + TB - 1) / TB;     // 391
    const int gridN8 = (NN * 8) / TB;          // 3125 (exact)
    const int gridE4 = (EG * 8) / TB;          // 12500 (exact)
    const int gridV4 = (EE / 4 + TB - 1) / TB; // 1563
    const int gridHS = 1184;

    k_init<<<gridN8, TB>>>();
    k_deg<<<gridV4, TB>>>(dst4);

    // ---- hop 1 ----
    k_prep<1, 0><<<gridN8, TB>>>(F4);          // NH(F) + deg-norm
    k_cos<<<gridE4, TB>>>(src4, dst4);         // keys + pass0 hist + scan
    k_hs12<12><<<gridHS, TB>>>();              // bits [12:24)
    k_hs12<0><<<gridHS, TB>>>();               // bits [0:12)
    k_scatter<0><<<gridE4, TB>>>(F4, Y1, src4, dst4);

    // ---- hop 2 (cosine scale-invariant; norm folded as norm^2) ----
    k_prep<0, 1><<<gridN8, TB>>>((const float4*)Y1);  // NH(Y1) + selector re-arm
    k_cos<<<gridE4, TB>>>(src4, dst4);
    k_hs12<12><<<gridHS, TB>>>();
    k_hs12<0><<<gridHS, TB>>>();
    k_scatter<1><<<gridE4, TB>>>((const float4*)Y1, Y2, src4, dst4);

    // ---- final: out = (Y2 * norm) @ W^T ----
    k_fc<<<gridN, TB>>>((const float4*)Y2, W, out);
}